// round 14
// baseline (speedup 1.0000x reference)
#include <cuda_runtime.h>
#include <cuda_fp16.h>
#include <cuda_pipeline.h>
#include <math.h>
#include <stdint.h>

#define BB 64
#define NN 512
#define KDIM 2048
#define NSTEPS 5

#define KCHUNK 64
#define NCHUNK (KDIM / KCHUNK)   // 32
#define MROWS 64                 // rows per tile (was 128)

#define LO_SCALE     16384.0f            // 2^14
#define LO_INV_SCALE (1.0f / 16384.0f)   // 2^-14

// smem tiles (halves), padded row stride 72 halves (144B)
#define T_STRIDE 72
#define AH_OFF 0                 // 64 x 72 halves = 9216 B
#define AL_OFF 9216
#define BH_OFF 18432             // 32 x 72 halves = 4608 B
#define BL_OFF 23040
#define STAGE_BYTES 27648        // x2 buffers = 55296

// ---------------------------------------------------------------------------
// Scratch
// ---------------------------------------------------------------------------
__device__ __half g_mhi[(size_t)BB * NN * 2 * KDIM];   // 268 MB
__device__ __half g_mlo[(size_t)BB * NN * 2 * KDIM];   // 268 MB (scaled 2^14)
__device__ __half g_Shi[(size_t)2 * BB * 32 * KDIM];   // 16 MB
__device__ __half g_Slo[(size_t)2 * BB * 32 * KDIM];   // 16 MB (scaled 2^14)
__device__ float g_ain [(size_t)BB * NN * 32];
__device__ float g_aout[(size_t)BB * NN * 32];
__device__ float g_h   [(size_t)BB * NN * 32];

// ---------------------------------------------------------------------------
// PTX helpers
// ---------------------------------------------------------------------------
__device__ __forceinline__ uint32_t smem_u32(const void* p) {
    uint32_t a;
    asm("{ .reg .u64 t; cvta.to.shared.u64 t, %1; cvt.u32.u64 %0, t; }"
        : "=r"(a) : "l"(p));
    return a;
}

__device__ __forceinline__ void mma_f16(float* d,
                                        const uint32_t* a,
                                        uint32_t b0, uint32_t b1)
{
    asm volatile(
        "mma.sync.aligned.m16n8k16.row.col.f32.f16.f16.f32 "
        "{%0,%1,%2,%3}, {%4,%5,%6,%7}, {%8,%9}, {%0,%1,%2,%3};"
        : "+f"(d[0]), "+f"(d[1]), "+f"(d[2]), "+f"(d[3])
        : "r"(a[0]), "r"(a[1]), "r"(a[2]), "r"(a[3]), "r"(b0), "r"(b1));
}

__device__ __forceinline__ void ldmx4(uint32_t* r, uint32_t addr) {
    asm volatile(
        "ldmatrix.sync.aligned.m8n8.x4.shared.b16 {%0,%1,%2,%3}, [%4];"
        : "=r"(r[0]), "=r"(r[1]), "=r"(r[2]), "=r"(r[3]) : "r"(addr));
}

// Split x = hi + lo*2^-14, lo stored SCALED to stay in fp16 normal range.
__device__ __forceinline__ void f16_split_scaled(float x, __half& hi, __half& lo) {
    hi = __float2half_rn(x);
    lo = __float2half_rn((x - __half2float(hi)) * LO_SCALE);
}

// split 8 floats into packed hi/lo uint4
__device__ __forceinline__ void split8(const float* xs, uint4& hq, uint4& lq) {
    __half h[8], l[8];
    #pragma unroll
    for (int i = 0; i < 8; i++) f16_split_scaled(xs[i], h[i], l[i]);
    uint32_t hp[4], lp[4];
    #pragma unroll
    for (int q = 0; q < 4; q++) {
        __half2 hh = __halves2half2(h[2*q], h[2*q+1]);
        __half2 ll = __halves2half2(l[2*q], l[2*q+1]);
        hp[q] = *(uint32_t*)&hh;
        lp[q] = *(uint32_t*)&ll;
    }
    hq = make_uint4(hp[0], hp[1], hp[2], hp[3]);
    lq = make_uint4(lp[0], lp[1], lp[2], lp[3]);
}

// ---------------------------------------------------------------------------
// Kernel 1: S projections. 256 blocks x 4 token-groups (W loaded ONCE/block).
// ---------------------------------------------------------------------------
__global__ void __launch_bounds__(256)
s_kernel(const float* __restrict__ h_in,
         const float* __restrict__ W_in,  const float* __restrict__ b_in,
         const float* __restrict__ W_out, const float* __restrict__ b_out,
         __half* __restrict__ Shi, __half* __restrict__ Slo)
{
    __shared__ float Ws[2][128][32];
    __shared__ float hs[32][36];

    const int tid = threadIdx.x;
    for (int i = tid; i < 128 * 32; i += 256) {
        Ws[0][i >> 5][i & 31] = W_in[i];
        Ws[1][i >> 5][i & 31] = W_out[i];
    }

    const int w = tid >> 5, lane = tid & 31;

    for (int it = 0; it < 4; it++) {
        const int token0 = blockIdx.x * 128 + it * 32;

        __syncthreads();
        {
            int r = tid >> 3, c = (tid & 7) * 4;
            *(float4*)&hs[r][c] =
                *(const float4*)&h_in[(size_t)(token0 + r) * 32 + c];
        }
        __syncthreads();

        float hreg[32];
        #pragma unroll
        for (int k = 0; k < 32; k++) hreg[k] = hs[lane][k];

        const int b = token0 >> 9;
        const int n = (token0 & 511) + lane;

        #pragma unroll
        for (int which = 0; which < 2; which++) {
            const float* bias = which ? b_out : b_in;
            #pragma unroll
            for (int jj = 0; jj < 16; jj++) {
                int j = w * 16 + jj;
                float acc = __ldg(&bias[j]);
                #pragma unroll
                for (int k4 = 0; k4 < 8; k4++) {
                    float4 wv = *(const float4*)&Ws[which][j][k4 * 4];
                    acc += hreg[k4*4+0] * wv.x;
                    acc += hreg[k4*4+1] * wv.y;
                    acc += hreg[k4*4+2] * wv.z;
                    acc += hreg[k4*4+3] * wv.w;
                }
                __half hi, lo;
                f16_split_scaled(acc, hi, lo);
                int hp = j >> 2, e = j & 3;
                size_t idx = (((size_t)which * BB + b) * 32 + hp) * KDIM
                             + e * 512 + n;
                Shi[idx] = hi;
                Slo[idx] = lo;
            }
        }
    }
}

// ---------------------------------------------------------------------------
// Shared GEMM compute body — ldmatrix fragment loads. Warp w owns rows
// [16w, 16w+16) of the 64-row tile (w in 0..3).
// ---------------------------------------------------------------------------
struct GemmCtx {
    float acch[4][4], mast[4][4], accm[4][4];
};

__device__ __forceinline__ void gemm_compute_chunk(
    GemmCtx& cx, char* db, int w, int lane)
{
    const uint32_t base = smem_u32(db);
    const uint32_t aoff =
        (uint32_t)(((16 * w + (lane & 15)) * T_STRIDE + ((lane >> 4) << 3)) * 2);
    const uint32_t ah_b = base + AH_OFF + aoff;
    const uint32_t al_b = base + AL_OFF + aoff;
    const uint32_t boff =
        (uint32_t)(((((lane >> 4) << 3) + (lane & 7)) * T_STRIDE
                    + (((lane >> 3) & 1) << 3)) * 2);
    const uint32_t bh_b = base + BH_OFF + boff;
    const uint32_t bl_b = base + BL_OFF + boff;
    const uint32_t PSTEP = 16 * T_STRIDE * 2;

    #pragma unroll
    for (int ks = 0; ks < 4; ks++) {
        const uint32_t ksb = ks * 32;
        uint32_t ah[4], al[4];
        ldmx4(ah, ah_b + ksb);
        ldmx4(al, al_b + ksb);

        #pragma unroll
        for (int p = 0; p < 2; p++) {
            uint32_t bh[4], bl[4];
            ldmx4(bh, bh_b + ksb + p * PSTEP);
            ldmx4(bl, bl_b + ksb + p * PSTEP);
            mma_f16(cx.acch[2*p],   ah, bh[0], bh[1]);
            mma_f16(cx.accm[2*p],   ah, bl[0], bl[1]);
            mma_f16(cx.accm[2*p],   al, bh[0], bh[1]);
            mma_f16(cx.acch[2*p+1], ah, bh[2], bh[3]);
            mma_f16(cx.accm[2*p+1], ah, bl[2], bl[3]);
            mma_f16(cx.accm[2*p+1], al, bh[2], bh[3]);
        }
    }
    #pragma unroll
    for (int n2 = 0; n2 < 4; n2++)
        #pragma unroll
        for (int q = 0; q < 4; q++) {
            cx.mast[n2][q] += cx.acch[n2][q];
            cx.acch[n2][q] = 0.f;
        }
}

__device__ __forceinline__ void gemm_epilogue(
    GemmCtx& cx, float* outp, int b, int nt, int w, int g, int tig)
{
    const int row0 = nt * MROWS + 16 * w + g;
    #pragma unroll
    for (int n2 = 0; n2 < 4; n2++) {
        int col = n2 * 8 + tig * 2;
        float v0 = cx.mast[n2][0] + cx.accm[n2][0] * LO_INV_SCALE;
        float v1 = cx.mast[n2][1] + cx.accm[n2][1] * LO_INV_SCALE;
        float v2 = cx.mast[n2][2] + cx.accm[n2][2] * LO_INV_SCALE;
        float v3 = cx.mast[n2][3] + cx.accm[n2][3] * LO_INV_SCALE;
        *(float2*)&outp[((size_t)(b * NN + row0))     * 32 + col] = make_float2(v0, v1);
        *(float2*)&outp[((size_t)(b * NN + row0 + 8)) * 32 + col] = make_float2(v2, v3);
    }
}

// ---------------------------------------------------------------------------
// Kernel 2a: steady-state GEMM. 64-row tiles, grid (8,2,64)=1024 CTAs,
// 128 threads, smem 54 KB -> 4 CTAs/SM, 1.2% tile imbalance.
// ---------------------------------------------------------------------------
__global__ void __launch_bounds__(128, 4)
gemm_kernel(const __half* __restrict__ mhi, const __half* __restrict__ mlo,
            const __half* __restrict__ Shi, const __half* __restrict__ Slo,
            float* __restrict__ ain, float* __restrict__ aout)
{
    extern __shared__ char smem[];

    const int b     = blockIdx.z;
    const int which = blockIdx.y;
    const int nt    = blockIdx.x;
    const int tid   = threadIdx.x;
    const int w     = tid >> 5;
    const int lane  = tid & 31;
    const int g     = lane >> 2;
    const int tig   = lane & 3;

    const __half* Sh = Shi + ((size_t)(which * BB + b) * 32) * KDIM;
    const __half* Sl = Slo + ((size_t)(which * BB + b) * 32) * KDIM;
    const size_t mbase = ((size_t)(b * NN + nt * MROWS)) * 4096
                         + (size_t)which * 2048;
    const __half* mh = mhi + mbase;
    const __half* ml = mlo + mbase;

    GemmCtx cx;
    #pragma unroll
    for (int i = 0; i < 4; i++)
        #pragma unroll
        for (int q = 0; q < 4; q++)
            { cx.acch[i][q] = 0.f; cx.mast[i][q] = 0.f; cx.accm[i][q] = 0.f; }

    auto stage = [&](int c, int buf) {
        char* db = smem + buf * STAGE_BYTES;
        __half* Ah = (__half*)(db + AH_OFF);
        __half* Al = (__half*)(db + AL_OFF);
        __half* Bh = (__half*)(db + BH_OFF);
        __half* Bl = (__half*)(db + BL_OFF);
        const int k0 = c * KCHUNK;
        // A: 64 rows x 8 segs = 512 slots / 128 thr = 4 each
        #pragma unroll
        for (int i = 0; i < 4; i++) {
            int slot = tid + 128 * i;
            int r = slot >> 3, s = slot & 7;
            size_t gsrc = (size_t)r * 4096 + k0 + s * 8;
            uint32_t d = (uint32_t)(r * T_STRIDE + s * 8);
            __pipeline_memcpy_async(&Ah[d], &mh[gsrc], 16);
            __pipeline_memcpy_async(&Al[d], &ml[gsrc], 16);
        }
        // B: 32 rows x 8 segs = 256 slots / 128 thr = 2 each
        #pragma unroll
        for (int i = 0; i < 2; i++) {
            int slot = tid + 128 * i;
            int r = slot >> 3, s = slot & 7;
            size_t gsrc = (size_t)r * KDIM + k0 + s * 8;
            uint32_t d = (uint32_t)(r * T_STRIDE + s * 8);
            __pipeline_memcpy_async(&Bh[d], &Sh[gsrc], 16);
            __pipeline_memcpy_async(&Bl[d], &Sl[gsrc], 16);
        }
        __pipeline_commit();
    };

    stage(0, 0);

    for (int c = 0; c < NCHUNK; c++) {
        const int buf = c & 1;
        if (c + 1 < NCHUNK) {
            stage(c + 1, buf ^ 1);
            __pipeline_wait_prior(1);
        } else {
            __pipeline_wait_prior(0);
        }
        __syncthreads();
        gemm_compute_chunk(cx, smem + buf * STAGE_BYTES, w, lane);
        __syncthreads();
    }

    gemm_epilogue(cx, which ? aout : ain, b, nt, w, g, tig);
}

// ---------------------------------------------------------------------------
// Kernel 2b: step-0 GEMM — stages m from fp32, splits in-register, AND
// writes the split halves to g_mhi/g_mlo for steps 1..4.
// ---------------------------------------------------------------------------
__global__ void __launch_bounds__(128, 4)
gemm_first_kernel(const float* __restrict__ m,
                  __half* __restrict__ mhi, __half* __restrict__ mlo,
                  const __half* __restrict__ Shi, const __half* __restrict__ Slo,
                  float* __restrict__ ain, float* __restrict__ aout)
{
    extern __shared__ char smem[];

    const int b     = blockIdx.z;
    const int which = blockIdx.y;
    const int nt    = blockIdx.x;
    const int tid   = threadIdx.x;
    const int w     = tid >> 5;
    const int lane  = tid & 31;
    const int g     = lane >> 2;
    const int tig   = lane & 3;

    const __half* Sh = Shi + ((size_t)(which * BB + b) * 32) * KDIM;
    const __half* Sl = Slo + ((size_t)(which * BB + b) * 32) * KDIM;
    const size_t mbase = ((size_t)(b * NN + nt * MROWS)) * 4096
                         + (size_t)which * 2048;
    const float* mb = m + mbase;
    __half* outh = mhi + mbase;
    __half* outl = mlo + mbase;

    GemmCtx cx;
    #pragma unroll
    for (int i = 0; i < 4; i++)
        #pragma unroll
        for (int q = 0; q < 4; q++)
            { cx.acch[i][q] = 0.f; cx.mast[i][q] = 0.f; cx.accm[i][q] = 0.f; }

    float4 pf[8];
    auto prefetch_m = [&](int c) {
        const int k0 = c * KCHUNK;
        #pragma unroll
        for (int i = 0; i < 4; i++) {
            int slot = tid + 128 * i;
            int r = slot >> 3, s = slot & 7;
            const float* src = &mb[(size_t)r * 4096 + k0 + s * 8];
            pf[2*i]   = *(const float4*)&src[0];
            pf[2*i+1] = *(const float4*)&src[4];
        }
    };

    prefetch_m(0);

    for (int c = 0; c < NCHUNK; c++) {
        const int buf = c & 1;
        char* db = smem + buf * STAGE_BYTES;
        __half* Ah = (__half*)(db + AH_OFF);
        __half* Al = (__half*)(db + AL_OFF);
        __half* Bh = (__half*)(db + BH_OFF);
        __half* Bl = (__half*)(db + BL_OFF);
        const int k0 = c * KCHUNK;

        #pragma unroll
        for (int i = 0; i < 4; i++) {
            int slot = tid + 128 * i;
            int r = slot >> 3, s = slot & 7;
            float xs[8] = {pf[2*i].x, pf[2*i].y, pf[2*i].z, pf[2*i].w,
                           pf[2*i+1].x, pf[2*i+1].y, pf[2*i+1].z, pf[2*i+1].w};
            uint4 hq, lq;
            split8(xs, hq, lq);
            uint32_t d = (uint32_t)(r * T_STRIDE + s * 8);
            *(uint4*)&Ah[d] = hq;
            *(uint4*)&Al[d] = lq;
            size_t gdst = (size_t)r * 4096 + k0 + s * 8;
            *(uint4*)&outh[gdst] = hq;
            *(uint4*)&outl[gdst] = lq;
        }

        #pragma unroll
        for (int i = 0; i < 2; i++) {
            int slot = tid + 128 * i;
            int r = slot >> 3, s = slot & 7;
            size_t gsrc = (size_t)r * KDIM + k0 + s * 8;
            uint32_t d = (uint32_t)(r * T_STRIDE + s * 8);
            __pipeline_memcpy_async(&Bh[d], &Sh[gsrc], 16);
            __pipeline_memcpy_async(&Bl[d], &Sl[gsrc], 16);
        }
        __pipeline_commit();

        if (c + 1 < NCHUNK) prefetch_m(c + 1);

        __pipeline_wait_prior(0);
        __syncthreads();
        gemm_compute_chunk(cx, db, w, lane);
        __syncthreads();
    }

    gemm_epilogue(cx, which ? aout : ain, b, nt, w, g, tig);
}

// ---------------------------------------------------------------------------
// Kernel 3: gates — float4 weights/cats
// ---------------------------------------------------------------------------
__device__ __forceinline__ float sigmoidf_(float x) {
    return 1.0f / (1.0f + expf(-x));
}

__global__ void __launch_bounds__(256)
gates_kernel(const float* __restrict__ h_in,
             const float* __restrict__ Wz, const float* __restrict__ bz,
             const float* __restrict__ Wr, const float* __restrict__ br,
             const float* __restrict__ Wt, const float* __restrict__ bt,
             const float* __restrict__ ain_, const float* __restrict__ aout_,
             float* __restrict__ hout)
{
    __shared__ float WzT[32][100];
    __shared__ float WrT[32][100];
    __shared__ float WtT[32][100];
    __shared__ float cats[8][8][100];

    const int tid = threadIdx.x;
    for (int i = tid; i < 32 * 24; i += 256) {
        int j = i / 24, k4 = i % 24;
        *(float4*)&WzT[j][k4 * 4] = *(const float4*)&Wz[j * 96 + k4 * 4];
        *(float4*)&WrT[j][k4 * 4] = *(const float4*)&Wr[j * 96 + k4 * 4];
        *(float4*)&WtT[j][k4 * 4] = *(const float4*)&Wt[j * 96 + k4 * 4];
    }
    __syncthreads();

    const int w = tid >> 5, lane = tid & 31;
    const int token0 = blockIdx.x * 64 + w * 8;

    float hj[8], az[8], ar[8], at[8];
    float bzv = __ldg(&bz[lane]);
    float brv = __ldg(&br[lane]);
    float btv = __ldg(&bt[lane]);

    #pragma unroll
    for (int t = 0; t < 8; t++) {
        size_t t32 = (size_t)(token0 + t) * 32;
        cats[w][t][lane]      = ain_ [t32 + lane];
        cats[w][t][32 + lane] = aout_[t32 + lane];
        hj[t] = h_in[t32 + lane];
        cats[w][t][64 + lane] = hj[t];
        az[t] = bzv; ar[t] = brv; at[t] = btv;
    }
    __syncwarp();

    #pragma unroll 4
    for (int k4 = 0; k4 < 16; k4++) {
        float4 wz = *(const float4*)&WzT[lane][k4 * 4];
        float4 wr = *(const float4*)&WrT[lane][k4 * 4];
        float4 wt = *(const float4*)&WtT[lane][k4 * 4];
        #pragma unroll
        for (int t = 0; t < 8; t++) {
            float4 cv = *(const float4*)&cats[w][t][k4 * 4];
            az[t] += cv.x * wz.x; az[t] += cv.y * wz.y;
            az[t] += cv.z * wz.z; az[t] += cv.w * wz.w;
            ar[t] += cv.x * wr.x; ar[t] += cv.y * wr.y;
            ar[t] += cv.z * wr.z; ar[t] += cv.w * wr.w;
            at[t] += cv.x * wt.x; at[t] += cv.y * wt.y;
            at[t] += cv.z * wt.z; at[t] += cv.w * wt.w;
        }
    }
    #pragma unroll 4
    for (int k4 = 16; k4 < 24; k4++) {
        float4 wz = *(const float4*)&WzT[lane][k4 * 4];
        float4 wr = *(const float4*)&WrT[lane][k4 * 4];
        #pragma unroll
        for (int t = 0; t < 8; t++) {
            float4 cv = *(const float4*)&cats[w][t][k4 * 4];
            az[t] += cv.x * wz.x; az[t] += cv.y * wz.y;
            az[t] += cv.z * wz.z; az[t] += cv.w * wz.w;
            ar[t] += cv.x * wr.x; ar[t] += cv.y * wr.y;
            ar[t] += cv.z * wr.z; ar[t] += cv.w * wr.w;
        }
    }

    #pragma unroll
    for (int t = 0; t < 8; t++) {
        float z = sigmoidf_(az[t]);
        float r = sigmoidf_(ar[t]);
        az[t] = z;
        cats[w][t][64 + lane] = r * hj[t];
    }
    __syncwarp();

    #pragma unroll 4
    for (int k4 = 16; k4 < 24; k4++) {
        float4 wt = *(const float4*)&WtT[lane][k4 * 4];
        #pragma unroll
        for (int t = 0; t < 8; t++) {
            float4 cv = *(const float4*)&cats[w][t][k4 * 4];
            at[t] += cv.x * wt.x; at[t] += cv.y * wt.y;
            at[t] += cv.z * wt.z; at[t] += cv.w * wt.w;
        }
    }

    #pragma unroll
    for (int t = 0; t < 8; t++) {
        float hhat = tanhf(at[t]);
        size_t t32 = (size_t)(token0 + t) * 32;
        hout[t32 + lane] = hj[t] + az[t] * (hhat - hj[t]);
    }
}

// ---------------------------------------------------------------------------
// Kernel 4: final head
// ---------------------------------------------------------------------------
__global__ void __launch_bounds__(512)
final_kernel(const float* __restrict__ hsrc,
             const float* __restrict__ a,
             const float* __restrict__ W1, const float* __restrict__ b1,
             const float* __restrict__ W2, const float* __restrict__ b2,
             float* __restrict__ out)
{
    __shared__ float W1s[33][32];
    __shared__ float hs[16][32];

    const int tid = threadIdx.x;
    for (int i = tid; i < 32 * 33; i += 512) {
        int j = i / 33, k = i % 33;
        W1s[k][j] = W1[i];
    }

    const int w = tid >> 5, lane = tid & 31;
    const int token = blockIdx.x * 16 + w;
    const size_t t32 = (size_t)token * 32;

    hs[w][lane] = hsrc[t32 + lane];
    __syncthreads();

    float acc = __ldg(&b1[lane]);
    #pragma unroll
    for (int k = 0; k < 32; k++)
        acc += hs[w][k] * W1s[k][lane];
    acc += __ldg(&a[token]) * W1s[32][lane];

    float v = tanhf(acc) * __ldg(&W2[lane]);
    #pragma unroll
    for (int off = 16; off > 0; off >>= 1)
        v += __shfl_down_sync(0xFFFFFFFFu, v, off);

    if (lane == 0)
        out[token] = v + __ldg(&b2[0]);
}

// ---------------------------------------------------------------------------
// Launch
// ---------------------------------------------------------------------------
extern "C" void kernel_launch(void* const* d_in, const int* in_sizes, int n_in,
                              void* d_out, int out_size)
{
    const float* x     = (const float*)d_in[0];
    const float* a     = (const float*)d_in[1];
    const float* m     = (const float*)d_in[2];
    const float* W_in  = (const float*)d_in[3];
    const float* b_in  = (const float*)d_in[4];
    const float* W_out = (const float*)d_in[5];
    const float* b_out = (const float*)d_in[6];
    const float* Wz    = (const float*)d_in[7];
    const float* bz    = (const float*)d_in[8];
    const float* Wr    = (const float*)d_in[9];
    const float* br    = (const float*)d_in[10];
    const float* Wt    = (const float*)d_in[11];
    const float* bt    = (const float*)d_in[12];
    const float* W1    = (const float*)d_in[13];
    const float* b1    = (const float*)d_in[14];
    const float* W2    = (const float*)d_in[15];
    const float* b2    = (const float*)d_in[16];
    float* out = (float*)d_out;

    __half *pmhi, *pmlo, *pShi, *pSlo;
    float *pain, *paout, *ph;
    cudaGetSymbolAddress((void**)&pmhi,  g_mhi);
    cudaGetSymbolAddress((void**)&pmlo,  g_mlo);
    cudaGetSymbolAddress((void**)&pShi,  g_Shi);
    cudaGetSymbolAddress((void**)&pSlo,  g_Slo);
    cudaGetSymbolAddress((void**)&pain,  g_ain);
    cudaGetSymbolAddress((void**)&paout, g_aout);
    cudaGetSymbolAddress((void**)&ph,    g_h);

    const int dyn_smem = 2 * STAGE_BYTES;   // 55296
    cudaFuncSetAttribute(gemm_kernel,
                         cudaFuncAttributeMaxDynamicSharedMemorySize, dyn_smem);
    cudaFuncSetAttribute(gemm_first_kernel,
                         cudaFuncAttributeMaxDynamicSharedMemorySize, dyn_smem);

    const int n_tokens = BB * NN;   // 32768

    const float* hsrc = x;
    for (int step = 0; step < NSTEPS; step++) {
        s_kernel<<<n_tokens / 128, 256>>>(hsrc, W_in, b_in, W_out, b_out,
                                          pShi, pSlo);

        dim3 ggrid(NN / MROWS, 2, BB);   // (8, 2, 64) = 1024 CTAs
        if (step == 0) {
            gemm_first_kernel<<<ggrid, 128, dyn_smem>>>(m, pmhi, pmlo,
                                                        pShi, pSlo, pain, paout);
        } else {
            gemm_kernel<<<ggrid, 128, dyn_smem>>>(pmhi, pmlo, pShi, pSlo,
                                                  pain, paout);
        }

        gates_kernel<<<n_tokens / 64, 256>>>(hsrc, Wz, bz, Wr, br, Wt, bt,
                                             pain, paout, ph);
        hsrc = ph;
    }

    final_kernel<<<n_tokens / 16, 512>>>(hsrc, a, W1, b1, W2, b2, out);
}